// round 6
// baseline (speedup 1.0000x reference)
#include <cuda_runtime.h>
#include <cuda_fp16.h>
#include <cuda_bf16.h>
#include <cstdint>

#define NN 100000
#define EE 1600000
#define HID 64
#define OC 32
#define EPSV 1e-5f
#define EB 6250          // hist blocks (EE/256)
#define WPREPB 48        // wprep blocks (3*4096/256)
#define SBLK 98          // scan blocks ((NN+1023)/1024)

// ---------------- scratch (device globals; zero-initialized at module load) ----------------
__device__ float  g_q[(size_t)NN * HID];
__device__ float  g_skip[(size_t)NN * HID];
__device__ float  g_x[(size_t)NN * HID];
__device__ __half g_kvh[(size_t)NN * 128];   // per node: k[64] halves then v[64] halves (256 B)
__device__ uint4  g_wf[3 * 4096];            // per layer: 4 sel x 4 kt x 8 nt x 32 lanes {bh0,bh1,bl0,bl1}

__device__ int g_cnt[NN];                    // zeroed by k_head at end of every call
__device__ int g_rowstart[NN + 1];
__device__ int g_cursor[NN];
__device__ int g_csrsrc[EE];
__device__ int g_bsum[128];

// ================= hist + W-frag prep fused (disjoint block ranges) =================
__global__ void k_hist_prep(const int* __restrict__ ei,
                            const float* __restrict__ Wq, const float* __restrict__ Wk,
                            const float* __restrict__ Wv, const float* __restrict__ Ws) {
    int b = blockIdx.x;
    if (b < EB) {
        int e = b * 256 + threadIdx.x;
        if (e < EE) atomicAdd(&g_cnt[ei[EE + e]], 1);
        return;
    }
    int t = (b - EB) * 256 + threadIdx.x;    // 0 .. 3*4096-1
    if (t >= 3 * 4096) return;
    int lane  = t & 31;
    int nt    = (t >> 5) & 7;
    int kt    = (t >> 8) & 3;
    int sel   = (t >> 10) & 3;
    int layer = t >> 12;
    const float* Wb = (sel == 0) ? Wq : (sel == 1) ? Wk : (sel == 2) ? Wv : Ws;
    const float* W = Wb + (size_t)layer * HID * HID;
    int grp = lane >> 2, tig = lane & 3;
    int n  = nt * 8 + grp;
    int k0 = kt * 16 + tig * 2;

    float b00 = W[k0 * 64 + n],       b01 = W[(k0 + 1) * 64 + n];
    float b10 = W[(k0 + 8) * 64 + n], b11 = W[(k0 + 9) * 64 + n];

    __nv_bfloat162 h0 = __floats2bfloat162_rn(b00, b01);
    __nv_bfloat162 h1 = __floats2bfloat162_rn(b10, b11);
    __nv_bfloat162 l0 = __floats2bfloat162_rn(b00 - __bfloat162float(h0.x),
                                              b01 - __bfloat162float(h0.y));
    __nv_bfloat162 l1 = __floats2bfloat162_rn(b10 - __bfloat162float(h1.x),
                                              b11 - __bfloat162float(h1.y));
    uint4 o;
    o.x = *(uint32_t*)&h0; o.y = *(uint32_t*)&h1;
    o.z = *(uint32_t*)&l0; o.w = *(uint32_t*)&l1;
    g_wf[t] = o;
}

// ================= scan stage 1: per-1024-block exclusive scan =================
__global__ void k_scan1() {
    __shared__ int sh[1024];
    int i = blockIdx.x * 1024 + threadIdx.x;
    int v = (i < NN) ? g_cnt[i] : 0;
    sh[threadIdx.x] = v;
    __syncthreads();
    for (int off = 1; off < 1024; off <<= 1) {
        int t = (threadIdx.x >= off) ? sh[threadIdx.x - off] : 0;
        __syncthreads();
        sh[threadIdx.x] += t;
        __syncthreads();
    }
    if (i < NN) g_rowstart[i] = sh[threadIdx.x] - v;
    if (threadIdx.x == 1023) g_bsum[blockIdx.x] = sh[1023];
}

// ================= scan fixup: each block re-scans the 98 block sums, applies =================
__global__ void k_scan_fix() {
    __shared__ int sh[128];
    int t = threadIdx.x;
    if (t < 128) sh[t] = (t < SBLK) ? g_bsum[t] : 0;
    __syncthreads();
    for (int off = 1; off < 128; off <<= 1) {
        int u = (t < 128 && t >= off) ? sh[t - off] : 0;
        __syncthreads();
        if (t < 128) sh[t] += u;
        __syncthreads();
    }
    __shared__ int pre[128];
    if (t < 128) pre[t] = sh[t] - ((t < SBLK) ? g_bsum[t] : 0);   // exclusive
    __syncthreads();
    int i = blockIdx.x * blockDim.x + t;
    if (i < NN) {
        int rs = g_rowstart[i] + pre[i >> 10];
        g_rowstart[i] = rs;
        g_cursor[i] = rs;
    }
    if (i == 0) g_rowstart[NN] = EE;
}

__global__ void k_scatter(const int* __restrict__ ei) {
    int e = blockIdx.x * blockDim.x + threadIdx.x;
    if (e >= EE) return;
    int s = ei[e], d = ei[EE + e];
    int pos = atomicAdd(&g_cursor[d], 1);
    g_csrsrc[pos] = s;
}

// ================= fused QKVS GEMM: bf16 hi/lo 3-pass, 64 rows/block, all 4 matrices =================
__device__ __forceinline__ void mma_bf16(float* c, uint32_t a0, uint32_t a1,
                                         uint32_t a2, uint32_t a3,
                                         uint32_t b0, uint32_t b1) {
    asm volatile("mma.sync.aligned.m16n8k16.row.col.f32.bf16.bf16.f32 "
                 "{%0,%1,%2,%3}, {%4,%5,%6,%7}, {%8,%9}, {%0,%1,%2,%3};"
                 : "+f"(c[0]), "+f"(c[1]), "+f"(c[2]), "+f"(c[3])
                 : "r"(a0), "r"(a1), "r"(a2), "r"(a3), "r"(b0), "r"(b1));
}

__device__ __forceinline__ void split_pair(float a, float b, uint32_t& hi, uint32_t& lo) {
    __nv_bfloat162 h = __floats2bfloat162_rn(a, b);
    __nv_bfloat162 l = __floats2bfloat162_rn(a - __bfloat162float(h.x),
                                             b - __bfloat162float(h.y));
    hi = *(uint32_t*)&h;
    lo = *(uint32_t*)&l;
}

__global__ void __launch_bounds__(256) k_gemm_fused(
        const float* __restrict__ xin, const uint4* __restrict__ wf,
        const float* __restrict__ bq, const float* __restrict__ bk,
        const float* __restrict__ bv, const float* __restrict__ bs) {
    __shared__ float xs[64 * 68];
    const float* x = xin ? xin : g_x;
    int row0 = blockIdx.x * 64;
    int t = threadIdx.x;

#pragma unroll
    for (int i = 0; i < 4; i++) {
        int idx = t + 256 * i;
        int r = idx >> 4, c4 = idx & 15;
        float4 val = make_float4(0.f, 0.f, 0.f, 0.f);
        if (row0 + r < NN) val = ((const float4*)(x + (size_t)(row0 + r) * 64))[c4];
        *(float4*)(&xs[r * 68 + c4 * 4]) = val;
    }
    __syncthreads();

    int wid = t >> 5, lane = t & 31;
    int tig = lane & 3, grp = lane >> 2;
    int cloc = wid * 8 + 2 * tig;

    float acc[4][4][4];
    {
        const float* biases[4] = {bq, bk, bv, bs};
#pragma unroll
        for (int sel = 0; sel < 4; sel++) {
            float b0 = biases[sel][cloc], b1 = biases[sel][cloc + 1];
#pragma unroll
            for (int mt = 0; mt < 4; mt++) {
                acc[sel][mt][0] = b0; acc[sel][mt][1] = b1;
                acc[sel][mt][2] = b0; acc[sel][mt][3] = b1;
            }
        }
    }

#pragma unroll
    for (int kt = 0; kt < 4; kt++) {
        uint4 bf[4];
#pragma unroll
        for (int sel = 0; sel < 4; sel++)
            bf[sel] = wf[((sel * 4 + kt) * 8 + wid) * 32 + lane];
        int k = kt * 16 + tig * 2;
#pragma unroll
        for (int mt = 0; mt < 4; mt++) {
            int r = mt * 16 + grp;
            float a00 = xs[r * 68 + k],           a01 = xs[r * 68 + k + 1];
            float a10 = xs[(r + 8) * 68 + k],     a11 = xs[(r + 8) * 68 + k + 1];
            float a20 = xs[r * 68 + k + 8],       a21 = xs[r * 68 + k + 9];
            float a30 = xs[(r + 8) * 68 + k + 8], a31 = xs[(r + 8) * 68 + k + 9];
            uint32_t h0, l0, h1, l1, h2, l2, h3, l3;
            split_pair(a00, a01, h0, l0);
            split_pair(a10, a11, h1, l1);
            split_pair(a20, a21, h2, l2);
            split_pair(a30, a31, h3, l3);
#pragma unroll
            for (int sel = 0; sel < 4; sel++) {
                mma_bf16(acc[sel][mt], h0, h1, h2, h3, bf[sel].x, bf[sel].y);
                mma_bf16(acc[sel][mt], h0, h1, h2, h3, bf[sel].z, bf[sel].w);
                mma_bf16(acc[sel][mt], l0, l1, l2, l3, bf[sel].x, bf[sel].y);
            }
        }
    }

#pragma unroll
    for (int sel = 0; sel < 4; sel++) {
#pragma unroll
        for (int mt = 0; mt < 4; mt++) {
            int r0g = row0 + mt * 16 + grp;
            int r1g = r0g + 8;
            float* a = acc[sel][mt];
            if (sel == 0) {
                if (r0g < NN) *(float2*)(g_q + (size_t)r0g * 64 + cloc) = make_float2(a[0], a[1]);
                if (r1g < NN) *(float2*)(g_q + (size_t)r1g * 64 + cloc) = make_float2(a[2], a[3]);
            } else if (sel == 3) {
                if (r0g < NN) *(float2*)(g_skip + (size_t)r0g * 64 + cloc) = make_float2(a[0], a[1]);
                if (r1g < NN) *(float2*)(g_skip + (size_t)r1g * 64 + cloc) = make_float2(a[2], a[3]);
            } else {
                int off = (sel == 2) ? 64 : 0;
                if (r0g < NN) *(__half2*)(g_kvh + (size_t)r0g * 128 + off + cloc) = __floats2half2_rn(a[0], a[1]);
                if (r1g < NN) *(__half2*)(g_kvh + (size_t)r1g * 128 + off + cloc) = __floats2half2_rn(a[2], a[3]);
            }
        }
    }
}

// ================= fused attention: warp/node, 16 edges in flight =================
__device__ __forceinline__ float dot8(const float4& qa, const float4& qb, const uint4& kk) {
    float2 k0 = __half22float2(*(__half2*)&kk.x);
    float2 k1 = __half22float2(*(__half2*)&kk.y);
    float2 k2 = __half22float2(*(__half2*)&kk.z);
    float2 k3 = __half22float2(*(__half2*)&kk.w);
    return qa.x * k0.x + qa.y * k0.y + qa.z * k1.x + qa.w * k1.y
         + qb.x * k2.x + qb.y * k2.y + qb.z * k3.x + qb.w * k3.y;
}
__device__ __forceinline__ void acc8(float* a, float ex, const uint4& vv) {
    float2 v0 = __half22float2(*(__half2*)&vv.x);
    float2 v1 = __half22float2(*(__half2*)&vv.y);
    float2 v2 = __half22float2(*(__half2*)&vv.z);
    float2 v3 = __half22float2(*(__half2*)&vv.w);
    a[0] = fmaf(ex, v0.x, a[0]); a[1] = fmaf(ex, v0.y, a[1]);
    a[2] = fmaf(ex, v1.x, a[2]); a[3] = fmaf(ex, v1.y, a[3]);
    a[4] = fmaf(ex, v2.x, a[4]); a[5] = fmaf(ex, v2.y, a[5]);
    a[6] = fmaf(ex, v3.x, a[6]); a[7] = fmaf(ex, v3.y, a[7]);
}

__global__ void k_attn(const float* __restrict__ bg, const float* __restrict__ bb,
                       const float* __restrict__ bm, const float* __restrict__ bvv) {
    int warp = (blockIdx.x * blockDim.x + threadIdx.x) >> 5;
    if (warp >= NN) return;
    int lane = threadIdx.x & 31;
    int g = lane >> 3, j = lane & 7;
    int node = warp;

    const float4* q4 = (const float4*)(g_q + (size_t)node * 64);
    float4 qa = q4[2 * j], qb = q4[2 * j + 1];

    int beg = g_rowstart[node];
    int end = g_rowstart[node + 1];

    float a[8] = {0.f, 0.f, 0.f, 0.f, 0.f, 0.f, 0.f, 0.f};
    float den = 0.f;
    int i = beg;

    // main loop: 16 edges in flight (4 independent quad batches)
    for (; i + 16 <= end; i += 16) {
        int sA = g_csrsrc[i + g];
        int sB = g_csrsrc[i + 4 + g];
        int sC = g_csrsrc[i + 8 + g];
        int sD = g_csrsrc[i + 12 + g];
        const uint4* kvA = (const uint4*)(g_kvh + (size_t)sA * 128);
        const uint4* kvB = (const uint4*)(g_kvh + (size_t)sB * 128);
        const uint4* kvC = (const uint4*)(g_kvh + (size_t)sC * 128);
        const uint4* kvD = (const uint4*)(g_kvh + (size_t)sD * 128);
        uint4 kA = kvA[j], kB = kvB[j], kC = kvC[j], kD = kvD[j];
        uint4 vA = kvA[8 + j], vB = kvB[8 + j], vC = kvC[8 + j], vD = kvD[8 + j];

        float pA = dot8(qa, qb, kA);
        float pB = dot8(qa, qb, kB);
        float pC = dot8(qa, qb, kC);
        float pD = dot8(qa, qb, kD);
        pA += __shfl_xor_sync(0xffffffffu, pA, 1);
        pB += __shfl_xor_sync(0xffffffffu, pB, 1);
        pC += __shfl_xor_sync(0xffffffffu, pC, 1);
        pD += __shfl_xor_sync(0xffffffffu, pD, 1);
        float eA = __expf(pA * 0.25f);
        float eB = __expf(pB * 0.25f);
        float eC = __expf(pC * 0.25f);
        float eD = __expf(pD * 0.25f);
        acc8(a, eA, vA);
        acc8(a, eB, vB);
        acc8(a, eC, vC);
        acc8(a, eD, vD);
        den += (eA + eB) + (eC + eD);
    }
    // remainder: masked quads
    for (; i < end; i += 4) {
        int eidx = i + g;
        bool act = eidx < end;
        int s = g_csrsrc[act ? eidx : beg];
        const uint4* kv = (const uint4*)(g_kvh + (size_t)s * 128);
        uint4 kk = kv[j];
        uint4 vv = kv[8 + j];
        float p = dot8(qa, qb, kk);
        p += __shfl_xor_sync(0xffffffffu, p, 1);
        float ex = act ? __expf(p * 0.25f) : 0.f;
        acc8(a, ex, vv);
        den += ex;
    }

    // reduce across the 4 edge groups
#pragma unroll
    for (int c = 0; c < 8; c++) {
        a[c] += __shfl_xor_sync(0xffffffffu, a[c], 8);
        a[c] += __shfl_xor_sync(0xffffffffu, a[c], 16);
    }
    den += __shfl_xor_sync(0xffffffffu, den, 8);
    den += __shfl_xor_sync(0xffffffffu, den, 16);

    if (g == 0) {
        float inv = (den > 0.f) ? __frcp_rn(den) : 0.f;
        float4 ska = ((const float4*)(g_skip + (size_t)node * 64))[2 * j];
        float4 skb = ((const float4*)(g_skip + (size_t)node * 64))[2 * j + 1];
        float4 bga = ((const float4*)bg)[2 * j],  bgb = ((const float4*)bg)[2 * j + 1];
        float4 bba = ((const float4*)bb)[2 * j],  bbb = ((const float4*)bb)[2 * j + 1];
        float4 bma = ((const float4*)bm)[2 * j],  bmb = ((const float4*)bm)[2 * j + 1];
        float4 bva = ((const float4*)bvv)[2 * j], bvb = ((const float4*)bvv)[2 * j + 1];
        float o[8];
        o[0] = a[0] * inv + ska.x; o[1] = a[1] * inv + ska.y;
        o[2] = a[2] * inv + ska.z; o[3] = a[3] * inv + ska.w;
        o[4] = a[4] * inv + skb.x; o[5] = a[5] * inv + skb.y;
        o[6] = a[6] * inv + skb.z; o[7] = a[7] * inv + skb.w;
        o[0] = fmaxf((o[0] - bma.x) * rsqrtf(bva.x + EPSV) * bga.x + bba.x, 0.f);
        o[1] = fmaxf((o[1] - bma.y) * rsqrtf(bva.y + EPSV) * bga.y + bba.y, 0.f);
        o[2] = fmaxf((o[2] - bma.z) * rsqrtf(bva.z + EPSV) * bga.z + bba.z, 0.f);
        o[3] = fmaxf((o[3] - bma.w) * rsqrtf(bva.w + EPSV) * bga.w + bba.w, 0.f);
        o[4] = fmaxf((o[4] - bmb.x) * rsqrtf(bvb.x + EPSV) * bgb.x + bbb.x, 0.f);
        o[5] = fmaxf((o[5] - bmb.y) * rsqrtf(bvb.y + EPSV) * bgb.y + bbb.y, 0.f);
        o[6] = fmaxf((o[6] - bmb.z) * rsqrtf(bvb.z + EPSV) * bgb.z + bbb.z, 0.f);
        o[7] = fmaxf((o[7] - bmb.w) * rsqrtf(bvb.w + EPSV) * bgb.w + bbb.w, 0.f);
        float4* xo = (float4*)(g_x + (size_t)node * 64);
        xo[2 * j]     = make_float4(o[0], o[1], o[2], o[3]);
        xo[2 * j + 1] = make_float4(o[4], o[5], o[6], o[7]);
    }
}

// ================= head GEMM (also re-zeros g_cnt for the next call) =================
__global__ void k_head(const float* __restrict__ Wh, const float* __restrict__ bh,
                       float* __restrict__ out) {
    __shared__ float xs[32 * 64];
    __shared__ float ws[64 * 32];
    int t = threadIdx.x;
    int gid = blockIdx.x * blockDim.x + t;
    if (gid < NN) g_cnt[gid] = 0;            // prep histogram for next launch
    if (gid + 800000 - 800000 < NN && blockIdx.x >= (NN + 255) / 256) {}  // (no-op)
    int node0 = blockIdx.x * 32;
    const float4* xsrc = (const float4*)(g_x + (size_t)node0 * 64);
    ((float4*)xs)[t]       = xsrc[t];
    ((float4*)xs)[t + 256] = xsrc[t + 256];
    ((float4*)ws)[t]       = ((const float4*)Wh)[t];
    ((float4*)ws)[t + 256] = ((const float4*)Wh)[t + 256];
    __syncthreads();
    int col = t & 31, nr = t >> 5;
    float a0, a1, a2, a3;
    a0 = a1 = a2 = a3 = bh[col];
#pragma unroll 8
    for (int kk = 0; kk < 64; kk++) {
        float w = ws[kk * 32 + col];
        a0 = fmaf(xs[nr * 64 + kk],        w, a0);
        a1 = fmaf(xs[(nr + 8) * 64 + kk],  w, a1);
        a2 = fmaf(xs[(nr + 16) * 64 + kk], w, a2);
        a3 = fmaf(xs[(nr + 24) * 64 + kk], w, a3);
    }
    out[(size_t)(node0 + nr) * 32 + col]      = a0;
    out[(size_t)(node0 + nr + 8) * 32 + col]  = a1;
    out[(size_t)(node0 + nr + 16) * 32 + col] = a2;
    out[(size_t)(node0 + nr + 24) * 32 + col] = a3;
}

// ================= launch =================
extern "C" void kernel_launch(void* const* d_in, const int* in_sizes, int n_in,
                              void* d_out, int out_size) {
    const float* x    = (const float*)d_in[0];
    const int*   ei   = (const int*)  d_in[1];
    const float* Wq   = (const float*)d_in[2];
    const float* bq   = (const float*)d_in[3];
    const float* Wk   = (const float*)d_in[4];
    const float* bk   = (const float*)d_in[5];
    const float* Wv   = (const float*)d_in[6];
    const float* bv   = (const float*)d_in[7];
    const float* Ws   = (const float*)d_in[8];
    const float* bs   = (const float*)d_in[9];
    const float* bn_g = (const float*)d_in[10];
    const float* bn_b = (const float*)d_in[11];
    const float* bn_m = (const float*)d_in[12];
    const float* bn_v = (const float*)d_in[13];
    const float* Wh   = (const float*)d_in[14];
    const float* bh   = (const float*)d_in[15];
    float* out = (float*)d_out;

    const int NB = (NN + 255) / 256;           // 391
    const int GA = (NN * 32 + 255) / 256;      // warp per node
    const int GH = NN / 32;                    // 3125 (GH*256 = 800000 >= NN for cnt zeroing)
    const int GR = (NN + 63) / 64;             // 1563

    uint4* wf_base;
    cudaGetSymbolAddress((void**)&wf_base, g_wf);

    // g_cnt is zero here: zero-initialized at load, then re-zeroed by k_head each call.
    k_hist_prep<<<EB + WPREPB, 256>>>(ei, Wq, Wk, Wv, Ws);   // 1
    k_scan1<<<SBLK, 1024>>>();                                // 2
    k_scan_fix<<<NB, 256>>>();                                // 3
    k_gemm_fused<<<GR, 256>>>(x, wf_base,                     // 4  <- profiled
                              bq, bk, bv, bs);
    k_scatter<<<EB, 256>>>(ei);                               // 5
    k_attn<<<GA, 256>>>(bn_g, bn_b, bn_m, bn_v);              // 6

    for (int l = 1; l < 3; l++) {
        size_t bo = (size_t)l * HID;
        k_gemm_fused<<<GR, 256>>>(nullptr, wf_base + (size_t)l * 4096,
                                  bq + bo, bk + bo, bv + bo, bs + bo);
        k_attn<<<GA, 256>>>(bn_g + bo, bn_b + bo, bn_m + bo, bn_v + bo);
    }
    k_head<<<GH, 256>>>(Wh, bh, out);
}

// round 7
// speedup vs baseline: 1.0779x; 1.0779x over previous
#include <cuda_runtime.h>
#include <cuda_fp16.h>
#include <cuda_bf16.h>
#include <cstdint>

#define NN 100000
#define EE 1600000
#define HID 64
#define OC 32
#define EPSV 1e-5f
#define EB 6250          // hist blocks (EE/256)
#define WPREPB 48        // wprep blocks (3*4096/256)
#define SBLK 98          // scan blocks ((NN+1023)/1024)

// ---------------- scratch (device globals; zero-initialized at module load) ----------------
__device__ float  g_q[(size_t)NN * HID];
__device__ float  g_skip[(size_t)NN * HID];
__device__ float  g_x[(size_t)NN * HID];
__device__ __half g_kvh[(size_t)NN * 128];   // per node: k[64] halves then v[64] halves (256 B)
__device__ uint4  g_wf[3 * 4096];            // per layer: 4 sel x 4 kt x 8 nt x 32 lanes {bh0,bh1,bl0,bl1}

__device__ int g_cnt[NN];                    // zeroed by k_head at end of every call
__device__ int g_rowstart[NN + 1];
__device__ int g_cursor[NN];
__device__ int g_csrsrc[EE];
__device__ int g_bsum[128];

// ================= hist + W-frag prep fused (disjoint block ranges) =================
__global__ void k_hist_prep(const int* __restrict__ ei,
                            const float* __restrict__ Wq, const float* __restrict__ Wk,
                            const float* __restrict__ Wv, const float* __restrict__ Ws) {
    int b = blockIdx.x;
    if (b < EB) {
        int e = b * 256 + threadIdx.x;
        if (e < EE) atomicAdd(&g_cnt[ei[EE + e]], 1);
        return;
    }
    int t = (b - EB) * 256 + threadIdx.x;    // 0 .. 3*4096-1
    if (t >= 3 * 4096) return;
    int lane  = t & 31;
    int nt    = (t >> 5) & 7;
    int kt    = (t >> 8) & 3;
    int sel   = (t >> 10) & 3;
    int layer = t >> 12;
    const float* Wb = (sel == 0) ? Wq : (sel == 1) ? Wk : (sel == 2) ? Wv : Ws;
    const float* W = Wb + (size_t)layer * HID * HID;
    int grp = lane >> 2, tig = lane & 3;
    int n  = nt * 8 + grp;
    int k0 = kt * 16 + tig * 2;

    float b00 = W[k0 * 64 + n],       b01 = W[(k0 + 1) * 64 + n];
    float b10 = W[(k0 + 8) * 64 + n], b11 = W[(k0 + 9) * 64 + n];

    __nv_bfloat162 h0 = __floats2bfloat162_rn(b00, b01);
    __nv_bfloat162 h1 = __floats2bfloat162_rn(b10, b11);
    __nv_bfloat162 l0 = __floats2bfloat162_rn(b00 - __bfloat162float(h0.x),
                                              b01 - __bfloat162float(h0.y));
    __nv_bfloat162 l1 = __floats2bfloat162_rn(b10 - __bfloat162float(h1.x),
                                              b11 - __bfloat162float(h1.y));
    uint4 o;
    o.x = *(uint32_t*)&h0; o.y = *(uint32_t*)&h1;
    o.z = *(uint32_t*)&l0; o.w = *(uint32_t*)&l1;
    g_wf[t] = o;
}

// ================= scan stage 1 =================
__global__ void k_scan1() {
    __shared__ int sh[1024];
    int i = blockIdx.x * 1024 + threadIdx.x;
    int v = (i < NN) ? g_cnt[i] : 0;
    sh[threadIdx.x] = v;
    __syncthreads();
    for (int off = 1; off < 1024; off <<= 1) {
        int t = (threadIdx.x >= off) ? sh[threadIdx.x - off] : 0;
        __syncthreads();
        sh[threadIdx.x] += t;
        __syncthreads();
    }
    if (i < NN) g_rowstart[i] = sh[threadIdx.x] - v;
    if (threadIdx.x == 1023) g_bsum[blockIdx.x] = sh[1023];
}

// ================= scan fixup =================
__global__ void k_scan_fix() {
    __shared__ int sh[128];
    int t = threadIdx.x;
    if (t < 128) sh[t] = (t < SBLK) ? g_bsum[t] : 0;
    __syncthreads();
    for (int off = 1; off < 128; off <<= 1) {
        int u = (t < 128 && t >= off) ? sh[t - off] : 0;
        __syncthreads();
        if (t < 128) sh[t] += u;
        __syncthreads();
    }
    __shared__ int pre[128];
    if (t < 128) pre[t] = sh[t] - ((t < SBLK) ? g_bsum[t] : 0);
    __syncthreads();
    int i = blockIdx.x * blockDim.x + t;
    if (i < NN) {
        int rs = g_rowstart[i] + pre[i >> 10];
        g_rowstart[i] = rs;
        g_cursor[i] = rs;
    }
    if (i == 0) g_rowstart[NN] = EE;
}

__global__ void k_scatter(const int* __restrict__ ei) {
    int e = blockIdx.x * blockDim.x + threadIdx.x;
    if (e >= EE) return;
    int s = ei[e], d = ei[EE + e];
    int pos = atomicAdd(&g_cursor[d], 1);
    g_csrsrc[pos] = s;
}

// ================= fused QKVS GEMM: bf16 hi/lo 3-pass, 32 rows/block, 2 CTAs/SM =================
__device__ __forceinline__ void mma_bf16(float* c, uint32_t a0, uint32_t a1,
                                         uint32_t a2, uint32_t a3,
                                         uint32_t b0, uint32_t b1) {
    asm volatile("mma.sync.aligned.m16n8k16.row.col.f32.bf16.bf16.f32 "
                 "{%0,%1,%2,%3}, {%4,%5,%6,%7}, {%8,%9}, {%0,%1,%2,%3};"
                 : "+f"(c[0]), "+f"(c[1]), "+f"(c[2]), "+f"(c[3])
                 : "r"(a0), "r"(a1), "r"(a2), "r"(a3), "r"(b0), "r"(b1));
}

__device__ __forceinline__ void split_pair(float a, float b, uint32_t& hi, uint32_t& lo) {
    __nv_bfloat162 h = __floats2bfloat162_rn(a, b);
    __nv_bfloat162 l = __floats2bfloat162_rn(a - __bfloat162float(h.x),
                                             b - __bfloat162float(h.y));
    hi = *(uint32_t*)&h;
    lo = *(uint32_t*)&l;
}

// grid 3125 (=NN/32 exactly), block 256, 2 CTAs/SM target.
__global__ void __launch_bounds__(256, 2) k_gemm_fused(
        const float* __restrict__ xin, const uint4* __restrict__ wf,
        const float* __restrict__ bq, const float* __restrict__ bk,
        const float* __restrict__ bv, const float* __restrict__ bs) {
    __shared__ float xs[32 * 68];
    const float* x = xin ? xin : g_x;
    int row0 = blockIdx.x * 32;
    int t = threadIdx.x;

#pragma unroll
    for (int i = 0; i < 2; i++) {
        int idx = t + 256 * i;               // 512 float4 = 32 rows x 16
        int r = idx >> 4, c4 = idx & 15;
        float4 val = ((const float4*)(x + (size_t)(row0 + r) * 64))[c4];
        *(float4*)(&xs[r * 68 + c4 * 4]) = val;
    }
    __syncthreads();

    int wid = t >> 5, lane = t & 31;
    int tig = lane & 3, grp = lane >> 2;
    int cloc = wid * 8 + 2 * tig;

    float acc[4][2][4];
    {
        const float* biases[4] = {bq, bk, bv, bs};
#pragma unroll
        for (int sel = 0; sel < 4; sel++) {
            float b0 = biases[sel][cloc], b1 = biases[sel][cloc + 1];
#pragma unroll
            for (int mt = 0; mt < 2; mt++) {
                acc[sel][mt][0] = b0; acc[sel][mt][1] = b1;
                acc[sel][mt][2] = b0; acc[sel][mt][3] = b1;
            }
        }
    }

#pragma unroll
    for (int kt = 0; kt < 4; kt++) {
        uint4 bf[4];
#pragma unroll
        for (int sel = 0; sel < 4; sel++)
            bf[sel] = wf[((sel * 4 + kt) * 8 + wid) * 32 + lane];
        int k = kt * 16 + tig * 2;
#pragma unroll
        for (int mt = 0; mt < 2; mt++) {
            int r = mt * 16 + grp;
            float a00 = xs[r * 68 + k],           a01 = xs[r * 68 + k + 1];
            float a10 = xs[(r + 8) * 68 + k],     a11 = xs[(r + 8) * 68 + k + 1];
            float a20 = xs[r * 68 + k + 8],       a21 = xs[r * 68 + k + 9];
            float a30 = xs[(r + 8) * 68 + k + 8], a31 = xs[(r + 8) * 68 + k + 9];
            uint32_t h0, l0, h1, l1, h2, l2, h3, l3;
            split_pair(a00, a01, h0, l0);
            split_pair(a10, a11, h1, l1);
            split_pair(a20, a21, h2, l2);
            split_pair(a30, a31, h3, l3);
#pragma unroll
            for (int sel = 0; sel < 4; sel++) {
                mma_bf16(acc[sel][mt], h0, h1, h2, h3, bf[sel].x, bf[sel].y);
                mma_bf16(acc[sel][mt], h0, h1, h2, h3, bf[sel].z, bf[sel].w);
                mma_bf16(acc[sel][mt], l0, l1, l2, l3, bf[sel].x, bf[sel].y);
            }
        }
    }

#pragma unroll
    for (int sel = 0; sel < 4; sel++) {
#pragma unroll
        for (int mt = 0; mt < 2; mt++) {
            int r0g = row0 + mt * 16 + grp;
            int r1g = r0g + 8;
            float* a = acc[sel][mt];
            if (sel == 0) {
                *(float2*)(g_q + (size_t)r0g * 64 + cloc) = make_float2(a[0], a[1]);
                *(float2*)(g_q + (size_t)r1g * 64 + cloc) = make_float2(a[2], a[3]);
            } else if (sel == 3) {
                *(float2*)(g_skip + (size_t)r0g * 64 + cloc) = make_float2(a[0], a[1]);
                *(float2*)(g_skip + (size_t)r1g * 64 + cloc) = make_float2(a[2], a[3]);
            } else {
                int off = (sel == 2) ? 64 : 0;
                *(__half2*)(g_kvh + (size_t)r0g * 128 + off + cloc) = __floats2half2_rn(a[0], a[1]);
                *(__half2*)(g_kvh + (size_t)r1g * 128 + off + cloc) = __floats2half2_rn(a[2], a[3]);
            }
        }
    }
}

// ================= fused attention: warp/node, 16 edges in flight =================
__device__ __forceinline__ float dot8(const float4& qa, const float4& qb, const uint4& kk) {
    float2 k0 = __half22float2(*(__half2*)&kk.x);
    float2 k1 = __half22float2(*(__half2*)&kk.y);
    float2 k2 = __half22float2(*(__half2*)&kk.z);
    float2 k3 = __half22float2(*(__half2*)&kk.w);
    return qa.x * k0.x + qa.y * k0.y + qa.z * k1.x + qa.w * k1.y
         + qb.x * k2.x + qb.y * k2.y + qb.z * k3.x + qb.w * k3.y;
}
__device__ __forceinline__ void acc8(float* a, float ex, const uint4& vv) {
    float2 v0 = __half22float2(*(__half2*)&vv.x);
    float2 v1 = __half22float2(*(__half2*)&vv.y);
    float2 v2 = __half22float2(*(__half2*)&vv.z);
    float2 v3 = __half22float2(*(__half2*)&vv.w);
    a[0] = fmaf(ex, v0.x, a[0]); a[1] = fmaf(ex, v0.y, a[1]);
    a[2] = fmaf(ex, v1.x, a[2]); a[3] = fmaf(ex, v1.y, a[3]);
    a[4] = fmaf(ex, v2.x, a[4]); a[5] = fmaf(ex, v2.y, a[5]);
    a[6] = fmaf(ex, v3.x, a[6]); a[7] = fmaf(ex, v3.y, a[7]);
}

__global__ void k_attn(const float* __restrict__ bg, const float* __restrict__ bb,
                       const float* __restrict__ bm, const float* __restrict__ bvv) {
    int warp = (blockIdx.x * blockDim.x + threadIdx.x) >> 5;
    if (warp >= NN) return;
    int lane = threadIdx.x & 31;
    int g = lane >> 3, j = lane & 7;
    int node = warp;

    const float4* q4 = (const float4*)(g_q + (size_t)node * 64);
    float4 qa = q4[2 * j], qb = q4[2 * j + 1];

    int beg = g_rowstart[node];
    int end = g_rowstart[node + 1];

    float a[8] = {0.f, 0.f, 0.f, 0.f, 0.f, 0.f, 0.f, 0.f};
    float den = 0.f;
    int i = beg;

    for (; i + 16 <= end; i += 16) {
        int sA = g_csrsrc[i + g];
        int sB = g_csrsrc[i + 4 + g];
        int sC = g_csrsrc[i + 8 + g];
        int sD = g_csrsrc[i + 12 + g];
        const uint4* kvA = (const uint4*)(g_kvh + (size_t)sA * 128);
        const uint4* kvB = (const uint4*)(g_kvh + (size_t)sB * 128);
        const uint4* kvC = (const uint4*)(g_kvh + (size_t)sC * 128);
        const uint4* kvD = (const uint4*)(g_kvh + (size_t)sD * 128);
        uint4 kA = kvA[j], kB = kvB[j], kC = kvC[j], kD = kvD[j];
        uint4 vA = kvA[8 + j], vB = kvB[8 + j], vC = kvC[8 + j], vD = kvD[8 + j];

        float pA = dot8(qa, qb, kA);
        float pB = dot8(qa, qb, kB);
        float pC = dot8(qa, qb, kC);
        float pD = dot8(qa, qb, kD);
        pA += __shfl_xor_sync(0xffffffffu, pA, 1);
        pB += __shfl_xor_sync(0xffffffffu, pB, 1);
        pC += __shfl_xor_sync(0xffffffffu, pC, 1);
        pD += __shfl_xor_sync(0xffffffffu, pD, 1);
        float eA = __expf(pA * 0.25f);
        float eB = __expf(pB * 0.25f);
        float eC = __expf(pC * 0.25f);
        float eD = __expf(pD * 0.25f);
        acc8(a, eA, vA);
        acc8(a, eB, vB);
        acc8(a, eC, vC);
        acc8(a, eD, vD);
        den += (eA + eB) + (eC + eD);
    }
    for (; i < end; i += 4) {
        int eidx = i + g;
        bool act = eidx < end;
        int s = g_csrsrc[act ? eidx : beg];
        const uint4* kv = (const uint4*)(g_kvh + (size_t)s * 128);
        uint4 kk = kv[j];
        uint4 vv = kv[8 + j];
        float p = dot8(qa, qb, kk);
        p += __shfl_xor_sync(0xffffffffu, p, 1);
        float ex = act ? __expf(p * 0.25f) : 0.f;
        acc8(a, ex, vv);
        den += ex;
    }

#pragma unroll
    for (int c = 0; c < 8; c++) {
        a[c] += __shfl_xor_sync(0xffffffffu, a[c], 8);
        a[c] += __shfl_xor_sync(0xffffffffu, a[c], 16);
    }
    den += __shfl_xor_sync(0xffffffffu, den, 8);
    den += __shfl_xor_sync(0xffffffffu, den, 16);

    if (g == 0) {
        float inv = (den > 0.f) ? __frcp_rn(den) : 0.f;
        float4 ska = ((const float4*)(g_skip + (size_t)node * 64))[2 * j];
        float4 skb = ((const float4*)(g_skip + (size_t)node * 64))[2 * j + 1];
        float4 bga = ((const float4*)bg)[2 * j],  bgb = ((const float4*)bg)[2 * j + 1];
        float4 bba = ((const float4*)bb)[2 * j],  bbb = ((const float4*)bb)[2 * j + 1];
        float4 bma = ((const float4*)bm)[2 * j],  bmb = ((const float4*)bm)[2 * j + 1];
        float4 bva = ((const float4*)bvv)[2 * j], bvb = ((const float4*)bvv)[2 * j + 1];
        float o[8];
        o[0] = a[0] * inv + ska.x; o[1] = a[1] * inv + ska.y;
        o[2] = a[2] * inv + ska.z; o[3] = a[3] * inv + ska.w;
        o[4] = a[4] * inv + skb.x; o[5] = a[5] * inv + skb.y;
        o[6] = a[6] * inv + skb.z; o[7] = a[7] * inv + skb.w;
        o[0] = fmaxf((o[0] - bma.x) * rsqrtf(bva.x + EPSV) * bga.x + bba.x, 0.f);
        o[1] = fmaxf((o[1] - bma.y) * rsqrtf(bva.y + EPSV) * bga.y + bba.y, 0.f);
        o[2] = fmaxf((o[2] - bma.z) * rsqrtf(bva.z + EPSV) * bga.z + bba.z, 0.f);
        o[3] = fmaxf((o[3] - bma.w) * rsqrtf(bva.w + EPSV) * bga.w + bba.w, 0.f);
        o[4] = fmaxf((o[4] - bmb.x) * rsqrtf(bvb.x + EPSV) * bgb.x + bbb.x, 0.f);
        o[5] = fmaxf((o[5] - bmb.y) * rsqrtf(bvb.y + EPSV) * bgb.y + bbb.y, 0.f);
        o[6] = fmaxf((o[6] - bmb.z) * rsqrtf(bvb.z + EPSV) * bgb.z + bbb.z, 0.f);
        o[7] = fmaxf((o[7] - bmb.w) * rsqrtf(bvb.w + EPSV) * bgb.w + bbb.w, 0.f);
        float4* xo = (float4*)(g_x + (size_t)node * 64);
        xo[2 * j]     = make_float4(o[0], o[1], o[2], o[3]);
        xo[2 * j + 1] = make_float4(o[4], o[5], o[6], o[7]);
    }
}

// ================= head GEMM (also re-zeros g_cnt for the next call) =================
__global__ void k_head(const float* __restrict__ Wh, const float* __restrict__ bh,
                       float* __restrict__ out) {
    __shared__ float xs[32 * 64];
    __shared__ float ws[64 * 32];
    int t = threadIdx.x;
    int gid = blockIdx.x * blockDim.x + t;
    if (gid < NN) g_cnt[gid] = 0;            // prep histogram for next call
    int node0 = blockIdx.x * 32;
    const float4* xsrc = (const float4*)(g_x + (size_t)node0 * 64);
    ((float4*)xs)[t]       = xsrc[t];
    ((float4*)xs)[t + 256] = xsrc[t + 256];
    ((float4*)ws)[t]       = ((const float4*)Wh)[t];
    ((float4*)ws)[t + 256] = ((const float4*)Wh)[t + 256];
    __syncthreads();
    int col = t & 31, nr = t >> 5;
    float a0, a1, a2, a3;
    a0 = a1 = a2 = a3 = bh[col];
#pragma unroll 8
    for (int kk = 0; kk < 64; kk++) {
        float w = ws[kk * 32 + col];
        a0 = fmaf(xs[nr * 64 + kk],        w, a0);
        a1 = fmaf(xs[(nr + 8) * 64 + kk],  w, a1);
        a2 = fmaf(xs[(nr + 16) * 64 + kk], w, a2);
        a3 = fmaf(xs[(nr + 24) * 64 + kk], w, a3);
    }
    out[(size_t)(node0 + nr) * 32 + col]      = a0;
    out[(size_t)(node0 + nr + 8) * 32 + col]  = a1;
    out[(size_t)(node0 + nr + 16) * 32 + col] = a2;
    out[(size_t)(node0 + nr + 24) * 32 + col] = a3;
}

// ================= launch =================
extern "C" void kernel_launch(void* const* d_in, const int* in_sizes, int n_in,
                              void* d_out, int out_size) {
    const float* x    = (const float*)d_in[0];
    const int*   ei   = (const int*)  d_in[1];
    const float* Wq   = (const float*)d_in[2];
    const float* bq   = (const float*)d_in[3];
    const float* Wk   = (const float*)d_in[4];
    const float* bk   = (const float*)d_in[5];
    const float* Wv   = (const float*)d_in[6];
    const float* bv   = (const float*)d_in[7];
    const float* Ws   = (const float*)d_in[8];
    const float* bs   = (const float*)d_in[9];
    const float* bn_g = (const float*)d_in[10];
    const float* bn_b = (const float*)d_in[11];
    const float* bn_m = (const float*)d_in[12];
    const float* bn_v = (const float*)d_in[13];
    const float* Wh   = (const float*)d_in[14];
    const float* bh   = (const float*)d_in[15];
    float* out = (float*)d_out;

    const int NB = (NN + 255) / 256;           // 391
    const int GA = (NN * 32 + 255) / 256;      // warp per node
    const int GH = NN / 32;                    // 3125
    const int GR = NN / 32;                    // 3125 (exact)

    uint4* wf_base;
    cudaGetSymbolAddress((void**)&wf_base, g_wf);

    k_hist_prep<<<EB + WPREPB, 256>>>(ei, Wq, Wk, Wv, Ws);   // 1
    k_scan1<<<SBLK, 1024>>>();                                // 2
    k_scan_fix<<<NB, 256>>>();                                // 3
    k_gemm_fused<<<GR, 256>>>(x, wf_base,                     // 4  <- profiled
                              bq, bk, bv, bs);
    k_scatter<<<EB, 256>>>(ei);                               // 5
    k_attn<<<GA, 256>>>(bn_g, bn_b, bn_m, bn_v);              // 6

    for (int l = 1; l < 3; l++) {
        size_t bo = (size_t)l * HID;
        k_gemm_fused<<<GR, 256>>>(nullptr, wf_base + (size_t)l * 4096,
                                  bq + bo, bk + bo, bv + bo, bs + bo);
        k_attn<<<GA, 256>>>(bn_g + bo, bn_b + bo, bn_m + bo, bn_v + bo);
    }
    k_head<<<GH, 256>>>(Wh, bh, out);
}

// round 8
// speedup vs baseline: 1.0781x; 1.0002x over previous
#include <cuda_runtime.h>
#include <cuda_fp16.h>
#include <cuda_bf16.h>
#include <cstdint>

#define NN 100000
#define EE 1600000
#define HID 64
#define OC 32
#define EPSV 1e-5f
#define EB 6250          // hist blocks (EE/256)
#define WPREPB 48        // wprep blocks (3*4096/256)
#define SBLK 98          // scan blocks ((NN+1023)/1024)

// ---------------- scratch (device globals; zero-initialized at module load) ----------------
__device__ float  g_q[(size_t)NN * HID];
__device__ float  g_skip[(size_t)NN * HID];
__device__ float  g_x[(size_t)NN * HID];
__device__ __half g_kvh[(size_t)NN * 128];   // per node: k[64] halves then v[64] halves (256 B)
__device__ uint4  g_wf[3 * 4096];            // per layer: 4 sel x 4 kt x 8 nt x 32 lanes {bh0,bh1,bl0,bl1}

__device__ int g_cnt[NN];                    // zeroed by k_head at end of every call
__device__ int g_rowstart[NN + 1];
__device__ int g_cursor[NN];
__device__ int g_csrsrc[EE];
__device__ int g_bsum[128];

// ================= hist + W-frag prep fused (disjoint block ranges) =================
__global__ void k_hist_prep(const int* __restrict__ ei,
                            const float* __restrict__ Wq, const float* __restrict__ Wk,
                            const float* __restrict__ Wv, const float* __restrict__ Ws) {
    int b = blockIdx.x;
    if (b < EB) {
        int e = b * 256 + threadIdx.x;
        if (e < EE) atomicAdd(&g_cnt[ei[EE + e]], 1);
        return;
    }
    int t = (b - EB) * 256 + threadIdx.x;    // 0 .. 3*4096-1
    if (t >= 3 * 4096) return;
    int lane  = t & 31;
    int nt    = (t >> 5) & 7;
    int kt    = (t >> 8) & 3;
    int sel   = (t >> 10) & 3;
    int layer = t >> 12;
    const float* Wb = (sel == 0) ? Wq : (sel == 1) ? Wk : (sel == 2) ? Wv : Ws;
    const float* W = Wb + (size_t)layer * HID * HID;
    int grp = lane >> 2, tig = lane & 3;
    int n  = nt * 8 + grp;
    int k0 = kt * 16 + tig * 2;

    float b00 = W[k0 * 64 + n],       b01 = W[(k0 + 1) * 64 + n];
    float b10 = W[(k0 + 8) * 64 + n], b11 = W[(k0 + 9) * 64 + n];

    __nv_bfloat162 h0 = __floats2bfloat162_rn(b00, b01);
    __nv_bfloat162 h1 = __floats2bfloat162_rn(b10, b11);
    __nv_bfloat162 l0 = __floats2bfloat162_rn(b00 - __bfloat162float(h0.x),
                                              b01 - __bfloat162float(h0.y));
    __nv_bfloat162 l1 = __floats2bfloat162_rn(b10 - __bfloat162float(h1.x),
                                              b11 - __bfloat162float(h1.y));
    uint4 o;
    o.x = *(uint32_t*)&h0; o.y = *(uint32_t*)&h1;
    o.z = *(uint32_t*)&l0; o.w = *(uint32_t*)&l1;
    g_wf[t] = o;
}

// ================= scan stage 1 =================
__global__ void k_scan1() {
    __shared__ int sh[1024];
    int i = blockIdx.x * 1024 + threadIdx.x;
    int v = (i < NN) ? g_cnt[i] : 0;
    sh[threadIdx.x] = v;
    __syncthreads();
    for (int off = 1; off < 1024; off <<= 1) {
        int t = (threadIdx.x >= off) ? sh[threadIdx.x - off] : 0;
        __syncthreads();
        sh[threadIdx.x] += t;
        __syncthreads();
    }
    if (i < NN) g_rowstart[i] = sh[threadIdx.x] - v;
    if (threadIdx.x == 1023) g_bsum[blockIdx.x] = sh[1023];
}

// ================= scan fixup =================
__global__ void k_scan_fix() {
    __shared__ int sh[128];
    int t = threadIdx.x;
    if (t < 128) sh[t] = (t < SBLK) ? g_bsum[t] : 0;
    __syncthreads();
    for (int off = 1; off < 128; off <<= 1) {
        int u = (t < 128 && t >= off) ? sh[t - off] : 0;
        __syncthreads();
        if (t < 128) sh[t] += u;
        __syncthreads();
    }
    __shared__ int pre[128];
    if (t < 128) pre[t] = sh[t] - ((t < SBLK) ? g_bsum[t] : 0);
    __syncthreads();
    int i = blockIdx.x * blockDim.x + t;
    if (i < NN) {
        int rs = g_rowstart[i] + pre[i >> 10];
        g_rowstart[i] = rs;
        g_cursor[i] = rs;
    }
    if (i == 0) g_rowstart[NN] = EE;
}

__global__ void k_scatter(const int* __restrict__ ei) {
    int e = blockIdx.x * blockDim.x + threadIdx.x;
    if (e >= EE) return;
    int s = ei[e], d = ei[EE + e];
    int pos = atomicAdd(&g_cursor[d], 1);
    g_csrsrc[pos] = s;
}

// ================= fused QKVS GEMM: pre-split bf16 hi/lo smem, 32 rows/block =================
__device__ __forceinline__ void mma_bf16(float* c, uint32_t a0, uint32_t a1,
                                         uint32_t a2, uint32_t a3,
                                         uint32_t b0, uint32_t b1) {
    asm volatile("mma.sync.aligned.m16n8k16.row.col.f32.bf16.bf16.f32 "
                 "{%0,%1,%2,%3}, {%4,%5,%6,%7}, {%8,%9}, {%0,%1,%2,%3};"
                 : "+f"(c[0]), "+f"(c[1]), "+f"(c[2]), "+f"(c[3])
                 : "r"(a0), "r"(a1), "r"(a2), "r"(a3), "r"(b0), "r"(b1));
}

__device__ __forceinline__ uint32_t pack_hi(float a, float b) {
    __nv_bfloat162 h = __floats2bfloat162_rn(a, b);
    return *(uint32_t*)&h;
}
__device__ __forceinline__ uint32_t pack_lo(float a, float b, uint32_t hi) {
    __nv_bfloat162 h = *(__nv_bfloat162*)&hi;
    __nv_bfloat162 l = __floats2bfloat162_rn(a - __bfloat162float(h.x),
                                             b - __bfloat162float(h.y));
    return *(uint32_t*)&l;
}

#define XSTR 72   // bf16 row stride: 144 B -> 4-bank shift per row, conflict-free

// grid 3125 (=NN/32 exactly), block 256, 2 CTAs/SM.
__global__ void __launch_bounds__(256, 2) k_gemm_fused(
        const float* __restrict__ xin, const uint4* __restrict__ wf,
        const float* __restrict__ bq, const float* __restrict__ bk,
        const float* __restrict__ bv, const float* __restrict__ bs) {
    __shared__ __nv_bfloat16 xh[32 * XSTR];
    __shared__ __nv_bfloat16 xl[32 * XSTR];
    const float* x = xin ? xin : g_x;
    int row0 = blockIdx.x * 32;
    int t = threadIdx.x;

    // stage + single hi/lo split per element
#pragma unroll
    for (int i = 0; i < 2; i++) {
        int idx = t + 256 * i;               // 512 float4 = 32 rows x 16
        int r = idx >> 4, c4 = idx & 15;
        float4 val = ((const float4*)(x + (size_t)(row0 + r) * 64))[c4];
        uint32_t h01 = pack_hi(val.x, val.y);
        uint32_t h23 = pack_hi(val.z, val.w);
        uint32_t l01 = pack_lo(val.x, val.y, h01);
        uint32_t l23 = pack_lo(val.z, val.w, h23);
        *(uint2*)(&xh[r * XSTR + c4 * 4]) = make_uint2(h01, h23);
        *(uint2*)(&xl[r * XSTR + c4 * 4]) = make_uint2(l01, l23);
    }
    __syncthreads();

    int wid = t >> 5, lane = t & 31;
    int tig = lane & 3, grp = lane >> 2;
    int cloc = wid * 8 + 2 * tig;

    float acc[4][2][4];
    {
        const float* biases[4] = {bq, bk, bv, bs};
#pragma unroll
        for (int sel = 0; sel < 4; sel++) {
            float b0 = biases[sel][cloc], b1 = biases[sel][cloc + 1];
#pragma unroll
            for (int mt = 0; mt < 2; mt++) {
                acc[sel][mt][0] = b0; acc[sel][mt][1] = b1;
                acc[sel][mt][2] = b0; acc[sel][mt][3] = b1;
            }
        }
    }

#pragma unroll
    for (int kt = 0; kt < 4; kt++) {
        uint4 bf[4];
#pragma unroll
        for (int sel = 0; sel < 4; sel++)
            bf[sel] = wf[((sel * 4 + kt) * 8 + wid) * 32 + lane];
        int k = kt * 16 + tig * 2;
#pragma unroll
        for (int mt = 0; mt < 2; mt++) {
            int r = mt * 16 + grp;
            uint32_t h0 = *(uint32_t*)&xh[r * XSTR + k];
            uint32_t h1 = *(uint32_t*)&xh[(r + 8) * XSTR + k];
            uint32_t h2 = *(uint32_t*)&xh[r * XSTR + k + 8];
            uint32_t h3 = *(uint32_t*)&xh[(r + 8) * XSTR + k + 8];
            uint32_t l0 = *(uint32_t*)&xl[r * XSTR + k];
            uint32_t l1 = *(uint32_t*)&xl[(r + 8) * XSTR + k];
            uint32_t l2 = *(uint32_t*)&xl[r * XSTR + k + 8];
            uint32_t l3 = *(uint32_t*)&xl[(r + 8) * XSTR + k + 8];
#pragma unroll
            for (int sel = 0; sel < 4; sel++) {
                mma_bf16(acc[sel][mt], h0, h1, h2, h3, bf[sel].x, bf[sel].y);
                mma_bf16(acc[sel][mt], h0, h1, h2, h3, bf[sel].z, bf[sel].w);
                mma_bf16(acc[sel][mt], l0, l1, l2, l3, bf[sel].x, bf[sel].y);
            }
        }
    }

#pragma unroll
    for (int sel = 0; sel < 4; sel++) {
#pragma unroll
        for (int mt = 0; mt < 2; mt++) {
            int r0g = row0 + mt * 16 + grp;
            int r1g = r0g + 8;
            float* a = acc[sel][mt];
            if (sel == 0) {
                *(float2*)(g_q + (size_t)r0g * 64 + cloc) = make_float2(a[0], a[1]);
                *(float2*)(g_q + (size_t)r1g * 64 + cloc) = make_float2(a[2], a[3]);
            } else if (sel == 3) {
                *(float2*)(g_skip + (size_t)r0g * 64 + cloc) = make_float2(a[0], a[1]);
                *(float2*)(g_skip + (size_t)r1g * 64 + cloc) = make_float2(a[2], a[3]);
            } else {
                int off = (sel == 2) ? 64 : 0;
                *(__half2*)(g_kvh + (size_t)r0g * 128 + off + cloc) = __floats2half2_rn(a[0], a[1]);
                *(__half2*)(g_kvh + (size_t)r1g * 128 + off + cloc) = __floats2half2_rn(a[2], a[3]);
            }
        }
    }
}

// ================= fused attention: uniform masked 16-edge batches =================
__device__ __forceinline__ float dot8(const float4& qa, const float4& qb, const uint4& kk) {
    float2 k0 = __half22float2(*(__half2*)&kk.x);
    float2 k1 = __half22float2(*(__half2*)&kk.y);
    float2 k2 = __half22float2(*(__half2*)&kk.z);
    float2 k3 = __half22float2(*(__half2*)&kk.w);
    return qa.x * k0.x + qa.y * k0.y + qa.z * k1.x + qa.w * k1.y
         + qb.x * k2.x + qb.y * k2.y + qb.z * k3.x + qb.w * k3.y;
}
__device__ __forceinline__ void acc8(float* a, float ex, const uint4& vv) {
    float2 v0 = __half22float2(*(__half2*)&vv.x);
    float2 v1 = __half22float2(*(__half2*)&vv.y);
    float2 v2 = __half22float2(*(__half2*)&vv.z);
    float2 v3 = __half22float2(*(__half2*)&vv.w);
    a[0] = fmaf(ex, v0.x, a[0]); a[1] = fmaf(ex, v0.y, a[1]);
    a[2] = fmaf(ex, v1.x, a[2]); a[3] = fmaf(ex, v1.y, a[3]);
    a[4] = fmaf(ex, v2.x, a[4]); a[5] = fmaf(ex, v2.y, a[5]);
    a[6] = fmaf(ex, v3.x, a[6]); a[7] = fmaf(ex, v3.y, a[7]);
}

__global__ void k_attn(const float* __restrict__ bg, const float* __restrict__ bb,
                       const float* __restrict__ bm, const float* __restrict__ bvv) {
    int warp = (blockIdx.x * blockDim.x + threadIdx.x) >> 5;
    if (warp >= NN) return;
    int lane = threadIdx.x & 31;
    int g = lane >> 3, j = lane & 7;
    int node = warp;

    const float4* q4 = (const float4*)(g_q + (size_t)node * 64);
    float4 qa = q4[2 * j], qb = q4[2 * j + 1];

    int beg = g_rowstart[node];
    int end = g_rowstart[node + 1];

    float a[8] = {0.f, 0.f, 0.f, 0.f, 0.f, 0.f, 0.f, 0.f};
    float den = 0.f;
    int lim = end - 1;

    // uniform masked 16-edge batches: all 8 gathers in flight per batch,
    // clamped indices keep every load unconditional.
    for (int i = beg; i < end; i += 16) {
        int iA = i + g, iB = i + 4 + g, iC = i + 8 + g, iD = i + 12 + g;
        int sA = g_csrsrc[min(iA, lim)];
        int sB = g_csrsrc[min(iB, lim)];
        int sC = g_csrsrc[min(iC, lim)];
        int sD = g_csrsrc[min(iD, lim)];
        const uint4* kvA = (const uint4*)(g_kvh + (size_t)sA * 128);
        const uint4* kvB = (const uint4*)(g_kvh + (size_t)sB * 128);
        const uint4* kvC = (const uint4*)(g_kvh + (size_t)sC * 128);
        const uint4* kvD = (const uint4*)(g_kvh + (size_t)sD * 128);
        uint4 kA = kvA[j], kB = kvB[j], kC = kvC[j], kD = kvD[j];
        uint4 vA = kvA[8 + j], vB = kvB[8 + j], vC = kvC[8 + j], vD = kvD[8 + j];

        float pA = dot8(qa, qb, kA);
        float pB = dot8(qa, qb, kB);
        float pC = dot8(qa, qb, kC);
        float pD = dot8(qa, qb, kD);
        pA += __shfl_xor_sync(0xffffffffu, pA, 1);
        pB += __shfl_xor_sync(0xffffffffu, pB, 1);
        pC += __shfl_xor_sync(0xffffffffu, pC, 1);
        pD += __shfl_xor_sync(0xffffffffu, pD, 1);
        float eA = (iA < end) ? __expf(pA * 0.25f) : 0.f;
        float eB = (iB < end) ? __expf(pB * 0.25f) : 0.f;
        float eC = (iC < end) ? __expf(pC * 0.25f) : 0.f;
        float eD = (iD < end) ? __expf(pD * 0.25f) : 0.f;
        acc8(a, eA, vA);
        acc8(a, eB, vB);
        acc8(a, eC, vC);
        acc8(a, eD, vD);
        den += (eA + eB) + (eC + eD);
    }

#pragma unroll
    for (int c = 0; c < 8; c++) {
        a[c] += __shfl_xor_sync(0xffffffffu, a[c], 8);
        a[c] += __shfl_xor_sync(0xffffffffu, a[c], 16);
    }
    den += __shfl_xor_sync(0xffffffffu, den, 8);
    den += __shfl_xor_sync(0xffffffffu, den, 16);

    if (g == 0) {
        float inv = (den > 0.f) ? __frcp_rn(den) : 0.f;
        float4 ska = ((const float4*)(g_skip + (size_t)node * 64))[2 * j];
        float4 skb = ((const float4*)(g_skip + (size_t)node * 64))[2 * j + 1];
        float4 bga = ((const float4*)bg)[2 * j],  bgb = ((const float4*)bg)[2 * j + 1];
        float4 bba = ((const float4*)bb)[2 * j],  bbb = ((const float4*)bb)[2 * j + 1];
        float4 bma = ((const float4*)bm)[2 * j],  bmb = ((const float4*)bm)[2 * j + 1];
        float4 bva = ((const float4*)bvv)[2 * j], bvb = ((const float4*)bvv)[2 * j + 1];
        float o[8];
        o[0] = a[0] * inv + ska.x; o[1] = a[1] * inv + ska.y;
        o[2] = a[2] * inv + ska.z; o[3] = a[3] * inv + ska.w;
        o[4] = a[4] * inv + skb.x; o[5] = a[5] * inv + skb.y;
        o[6] = a[6] * inv + skb.z; o[7] = a[7] * inv + skb.w;
        o[0] = fmaxf((o[0] - bma.x) * rsqrtf(bva.x + EPSV) * bga.x + bba.x, 0.f);
        o[1] = fmaxf((o[1] - bma.y) * rsqrtf(bva.y + EPSV) * bga.y + bba.y, 0.f);
        o[2] = fmaxf((o[2] - bma.z) * rsqrtf(bva.z + EPSV) * bga.z + bba.z, 0.f);
        o[3] = fmaxf((o[3] - bma.w) * rsqrtf(bva.w + EPSV) * bga.w + bba.w, 0.f);
        o[4] = fmaxf((o[4] - bmb.x) * rsqrtf(bvb.x + EPSV) * bgb.x + bbb.x, 0.f);
        o[5] = fmaxf((o[5] - bmb.y) * rsqrtf(bvb.y + EPSV) * bgb.y + bbb.y, 0.f);
        o[6] = fmaxf((o[6] - bmb.z) * rsqrtf(bvb.z + EPSV) * bgb.z + bbb.z, 0.f);
        o[7] = fmaxf((o[7] - bmb.w) * rsqrtf(bvb.w + EPSV) * bgb.w + bbb.w, 0.f);
        float4* xo = (float4*)(g_x + (size_t)node * 64);
        xo[2 * j]     = make_float4(o[0], o[1], o[2], o[3]);
        xo[2 * j + 1] = make_float4(o[4], o[5], o[6], o[7]);
    }
}

// ================= head GEMM (also re-zeros g_cnt for the next call) =================
__global__ void k_head(const float* __restrict__ Wh, const float* __restrict__ bh,
                       float* __restrict__ out) {
    __shared__ float xs[32 * 64];
    __shared__ float ws[64 * 32];
    int t = threadIdx.x;
    int gid = blockIdx.x * blockDim.x + t;
    if (gid < NN) g_cnt[gid] = 0;            // prep histogram for next call
    int node0 = blockIdx.x * 32;
    const float4* xsrc = (const float4*)(g_x + (size_t)node0 * 64);
    ((float4*)xs)[t]       = xsrc[t];
    ((float4*)xs)[t + 256] = xsrc[t + 256];
    ((float4*)ws)[t]       = ((const float4*)Wh)[t];
    ((float4*)ws)[t + 256] = ((const float4*)Wh)[t + 256];
    __syncthreads();
    int col = t & 31, nr = t >> 5;
    float a0, a1, a2, a3;
    a0 = a1 = a2 = a3 = bh[col];
#pragma unroll 8
    for (int kk = 0; kk < 64; kk++) {
        float w = ws[kk * 32 + col];
        a0 = fmaf(xs[nr * 64 + kk],        w, a0);
        a1 = fmaf(xs[(nr + 8) * 64 + kk],  w, a1);
        a2 = fmaf(xs[(nr + 16) * 64 + kk], w, a2);
        a3 = fmaf(xs[(nr + 24) * 64 + kk], w, a3);
    }
    out[(size_t)(node0 + nr) * 32 + col]      = a0;
    out[(size_t)(node0 + nr + 8) * 32 + col]  = a1;
    out[(size_t)(node0 + nr + 16) * 32 + col] = a2;
    out[(size_t)(node0 + nr + 24) * 32 + col] = a3;
}

// ================= launch =================
extern "C" void kernel_launch(void* const* d_in, const int* in_sizes, int n_in,
                              void* d_out, int out_size) {
    const float* x    = (const float*)d_in[0];
    const int*   ei   = (const int*)  d_in[1];
    const float* Wq   = (const float*)d_in[2];
    const float* bq   = (const float*)d_in[3];
    const float* Wk   = (const float*)d_in[4];
    const float* bk   = (const float*)d_in[5];
    const float* Wv   = (const float*)d_in[6];
    const float* bv   = (const float*)d_in[7];
    const float* Ws   = (const float*)d_in[8];
    const float* bs   = (const float*)d_in[9];
    const float* bn_g = (const float*)d_in[10];
    const float* bn_b = (const float*)d_in[11];
    const float* bn_m = (const float*)d_in[12];
    const float* bn_v = (const float*)d_in[13];
    const float* Wh   = (const float*)d_in[14];
    const float* bh   = (const float*)d_in[15];
    float* out = (float*)d_out;

    const int NB = (NN + 255) / 256;           // 391
    const int GA = (NN * 32 + 255) / 256;      // warp per node
    const int GH = NN / 32;                    // 3125
    const int GR = NN / 32;                    // 3125 (exact)

    uint4* wf_base;
    cudaGetSymbolAddress((void**)&wf_base, g_wf);

    k_hist_prep<<<EB + WPREPB, 256>>>(ei, Wq, Wk, Wv, Ws);   // 1
    k_scan1<<<SBLK, 1024>>>();                                // 2
    k_scan_fix<<<NB, 256>>>();                                // 3
    k_gemm_fused<<<GR, 256>>>(x, wf_base,                     // 4  <- profiled
                              bq, bk, bv, bs);
    k_scatter<<<EB, 256>>>(ei);                               // 5
    k_attn<<<GA, 256>>>(bn_g, bn_b, bn_m, bn_v);              // 6

    for (int l = 1; l < 3; l++) {
        size_t bo = (size_t)l * HID;
        k_gemm_fused<<<GR, 256>>>(nullptr, wf_base + (size_t)l * 4096,
                                  bq + bo, bk + bo, bv + bo, bs + bo);
        k_attn<<<GA, 256>>>(bn_g + bo, bn_b + bo, bn_m + bo, bn_v + bo);
    }
    k_head<<<GH, 256>>>(Wh, bh, out);
}